// round 1
// baseline (speedup 1.0000x reference)
#include <cuda_runtime.h>
#include <cuda_bf16.h>

#define N_NODES  100000
#define N_EDGES  600000
#define N_GRAPHS 256
#define HID      128
#define IN_DIM   7
#define BN_EPS   1e-5f

// ---------------- scratch (static device globals; no allocs allowed) --------
__device__ float g_buf0[N_NODES * HID];   // h / agg buffer
__device__ float g_buf1[N_NODES * HID];   // hl buffer
__device__ float g_dinv[N_NODES];         // deg -> rsqrt(deg)
__device__ float g_pool[N_GRAPHS * HID];
__device__ float g_cnt[N_GRAPHS];
__device__ float g_p[64];                 // pocket embedding
__device__ float g_bns[3][HID];           // BN scale  = gamma * rsqrt(var+eps)
__device__ float g_bnb[3][HID];           // BN shift  = beta - mean*scale

// ---------------- tiny prep kernels ----------------------------------------
__global__ void k_bnprep(const float* __restrict__ gamma, const float* __restrict__ beta,
                         const float* __restrict__ mean,  const float* __restrict__ var) {
    int t = threadIdx.x;
    if (t < 3 * HID) {
        float s = gamma[t] * rsqrtf(var[t] + BN_EPS);
        ((float*)g_bns)[t] = s;
        ((float*)g_bnb)[t] = beta[t] - mean[t] * s;
    }
}

__global__ void k_deg_init() {
    int i = blockIdx.x * blockDim.x + threadIdx.x;
    if (i < N_NODES) g_dinv[i] = 1.0f;   // self-loop
}

__global__ void k_deg_count(const int* __restrict__ dst) {
    int i = blockIdx.x * blockDim.x + threadIdx.x;
    if (i < N_EDGES) atomicAdd(&g_dinv[dst[i]], 1.0f);
}

__global__ void k_deg_rsqrt() {
    int i = blockIdx.x * blockDim.x + threadIdx.x;
    if (i < N_NODES) g_dinv[i] = rsqrtf(g_dinv[i]);
}

__global__ void k_zero_pool() {
    int i = blockIdx.x * blockDim.x + threadIdx.x;
    if (i < N_GRAPHS * HID) g_pool[i] = 0.0f;
    else if (i < N_GRAPHS * HID + N_GRAPHS) g_cnt[i - N_GRAPHS * HID] = 0.0f;
}

// pocket MLP: 28 -> 64 (relu) -> 64 ; one block of 64 threads
__global__ void k_pocket(const float* __restrict__ pocket,
                         const float* __restrict__ pw1, const float* __restrict__ pb1,
                         const float* __restrict__ pw2, const float* __restrict__ pb2) {
    __shared__ float t[64];
    int j = threadIdx.x;
    float a = pb1[j];
    #pragma unroll
    for (int k = 0; k < 28; ++k) a = fmaf(pocket[k], pw1[k * 64 + j], a);
    t[j] = fmaxf(a, 0.0f);
    __syncthreads();
    float b = pb2[j];
    #pragma unroll
    for (int k = 0; k < 64; ++k) b = fmaf(t[k], pw2[k * 64 + j], b);
    g_p[j] = b;
}

// ---------------- layer 0 GEMM: x[N,7] @ W0[7,128] -------------------------
// writes hl -> g_buf1 and agg-init (hl*selfnorm + bias) -> g_buf0
__global__ void k_gemm0(const float* __restrict__ x, const float* __restrict__ W0,
                        const float* __restrict__ b0) {
    __shared__ float Ws[IN_DIM * HID];
    int tid = threadIdx.x;
    for (int i = tid; i < IN_DIM * HID; i += 256) Ws[i] = W0[i];
    __syncthreads();

    int node = blockIdx.x * 8 + (tid >> 5);
    int col  = (tid & 31) * 4;
    if (node >= N_NODES) return;

    float xr[IN_DIM];
    #pragma unroll
    for (int i = 0; i < IN_DIM; ++i) xr[i] = __ldg(&x[node * IN_DIM + i]);

    float4 acc = make_float4(0.f, 0.f, 0.f, 0.f);
    #pragma unroll
    for (int i = 0; i < IN_DIM; ++i) {
        float4 w = *(const float4*)&Ws[i * HID + col];
        acc.x = fmaf(xr[i], w.x, acc.x);
        acc.y = fmaf(xr[i], w.y, acc.y);
        acc.z = fmaf(xr[i], w.z, acc.z);
        acc.w = fmaf(xr[i], w.w, acc.w);
    }
    *(float4*)(g_buf1 + node * HID + col) = acc;
    float dv = g_dinv[node]; float sn = dv * dv;
    float4 b4 = *(const float4*)(b0 + col);
    float4 w4 = make_float4(fmaf(acc.x, sn, b4.x), fmaf(acc.y, sn, b4.y),
                            fmaf(acc.z, sn, b4.z), fmaf(acc.w, sn, b4.w));
    *(float4*)(g_buf0 + node * HID + col) = w4;
}

// ---------------- 128x128 GEMM with fused BN+ReLU on A-load ------------------
// A = g_buf0 (raw agg of prev layer), apply BN[bn_layer]+ReLU on load.
// Writes hl -> g_buf1, agg-init -> g_buf0 (in place; block reads only its rows,
// all reads precede the epilogue writes).
__global__ void __launch_bounds__(256, 4)
k_gemm128(const float* __restrict__ W, const float* __restrict__ bias, int bn_layer) {
    __shared__ float As[16][68];
    __shared__ float Bs[16][128];

    int row0 = blockIdx.x * 64;
    int tid = threadIdx.x;
    int tx = tid & 31;         // 32 column-groups of 4
    int ty = tid >> 5;         // 8 row-groups of 8

    float acc[8][4];
    #pragma unroll
    for (int r = 0; r < 8; ++r)
        #pragma unroll
        for (int c = 0; c < 4; ++c) acc[r][c] = 0.f;

    const float* bns = g_bns[bn_layer];
    const float* bnb = g_bnb[bn_layer];

    for (int k0 = 0; k0 < HID; k0 += 16) {
        // B chunk: 16x128 floats = 512 float4, 2 per thread (coalesced)
        const float4* Wv = (const float4*)(W + k0 * HID);
        ((float4*)&Bs[0][0])[tid]       = Wv[tid];
        ((float4*)&Bs[0][0])[tid + 256] = Wv[tid + 256];

        // A chunk transposed into As[k][m], with BN+ReLU applied
        int m  = tid >> 2;
        int kg = (tid & 3) * 4;
        int row = row0 + m;
        float4 a4 = make_float4(0.f, 0.f, 0.f, 0.f);
        if (row < N_NODES) a4 = *(const float4*)(g_buf0 + row * HID + k0 + kg);
        int kgl = k0 + kg;
        As[kg + 0][m] = fmaxf(fmaf(a4.x, bns[kgl + 0], bnb[kgl + 0]), 0.f);
        As[kg + 1][m] = fmaxf(fmaf(a4.y, bns[kgl + 1], bnb[kgl + 1]), 0.f);
        As[kg + 2][m] = fmaxf(fmaf(a4.z, bns[kgl + 2], bnb[kgl + 2]), 0.f);
        As[kg + 3][m] = fmaxf(fmaf(a4.w, bns[kgl + 3], bnb[kgl + 3]), 0.f);
        __syncthreads();

        #pragma unroll
        for (int kk = 0; kk < 16; ++kk) {
            float4 b  = *(const float4*)&Bs[kk][tx * 4];
            float4 a0 = *(const float4*)&As[kk][ty * 8];
            float4 a1 = *(const float4*)&As[kk][ty * 8 + 4];
            float a[8] = {a0.x, a0.y, a0.z, a0.w, a1.x, a1.y, a1.z, a1.w};
            #pragma unroll
            for (int r = 0; r < 8; ++r) {
                acc[r][0] = fmaf(a[r], b.x, acc[r][0]);
                acc[r][1] = fmaf(a[r], b.y, acc[r][1]);
                acc[r][2] = fmaf(a[r], b.z, acc[r][2]);
                acc[r][3] = fmaf(a[r], b.w, acc[r][3]);
            }
        }
        __syncthreads();
    }

    int col = tx * 4;
    float4 b4 = *(const float4*)(bias + col);
    #pragma unroll
    for (int r = 0; r < 8; ++r) {
        int row = row0 + ty * 8 + r;
        if (row >= N_NODES) break;
        float4 v = make_float4(acc[r][0], acc[r][1], acc[r][2], acc[r][3]);
        *(float4*)(g_buf1 + row * HID + col) = v;
        float dv = g_dinv[row]; float sn = dv * dv;
        float4 w = make_float4(fmaf(v.x, sn, b4.x), fmaf(v.y, sn, b4.y),
                               fmaf(v.z, sn, b4.z), fmaf(v.w, sn, b4.w));
        *(float4*)(g_buf0 + row * HID + col) = w;
    }
}

// ---------------- edge scatter: agg[dst] += hl[src] * dinv[s]*dinv[d] -------
// one warp per edge, float4 lanes, 16B vector reductions (1 LTS op per 16B)
__global__ void k_scatter(const int* __restrict__ src, const int* __restrict__ dst) {
    int e = blockIdx.x * 8 + (threadIdx.x >> 5);
    if (e >= N_EDGES) return;
    int l = threadIdx.x & 31;
    int s = src[e], d = dst[e];
    float norm = g_dinv[s] * g_dinv[d];
    float4 v = ((const float4*)g_buf1)[s * 32 + l];
    v.x *= norm; v.y *= norm; v.z *= norm; v.w *= norm;
    float* p = g_buf0 + d * HID + l * 4;
    asm volatile("red.global.add.v4.f32 [%0], {%1, %2, %3, %4};"
                 :: "l"(p), "f"(v.x), "f"(v.y), "f"(v.z), "f"(v.w) : "memory");
}

// ---------------- pooling: BN2+ReLU then segment-sum per graph --------------
__global__ void k_pool(const int* __restrict__ batch) {
    int node = blockIdx.x * 8 + (threadIdx.x >> 5);
    if (node >= N_NODES) return;
    int l = threadIdx.x & 31;
    int b = batch[node];
    float4 v  = ((const float4*)g_buf0)[node * 32 + l];
    float4 sc = ((const float4*)g_bns[2])[l];
    float4 sh = ((const float4*)g_bnb[2])[l];
    v.x = fmaxf(fmaf(v.x, sc.x, sh.x), 0.f);
    v.y = fmaxf(fmaf(v.y, sc.y, sh.y), 0.f);
    v.z = fmaxf(fmaf(v.z, sc.z, sh.z), 0.f);
    v.w = fmaxf(fmaf(v.w, sc.w, sh.w), 0.f);
    float* p = g_pool + b * HID + l * 4;
    asm volatile("red.global.add.v4.f32 [%0], {%1, %2, %3, %4};"
                 :: "l"(p), "f"(v.x), "f"(v.y), "f"(v.z), "f"(v.w) : "memory");
    if (l == 0) atomicAdd(&g_cnt[b], 1.0f);
}

// ---------------- head: mean, concat pocket, 192->96 relu ->1 ---------------
__global__ void k_head(const float* __restrict__ cw1, const float* __restrict__ cb1,
                       const float* __restrict__ cw2, const float* __restrict__ cb2,
                       float* __restrict__ out) {
    __shared__ float emb[192];
    __shared__ float hid[96];
    int g = blockIdx.x;
    int j = threadIdx.x;
    float inv = 1.0f / fmaxf(g_cnt[g], 1.0f);
    for (int idx = j; idx < 192; idx += 96)
        emb[idx] = (idx < HID) ? g_pool[g * HID + idx] * inv : g_p[idx - HID];
    __syncthreads();
    float a = cb1[j];
    #pragma unroll 8
    for (int k = 0; k < 192; ++k) a = fmaf(emb[k], cw1[k * 96 + j], a);
    hid[j] = fmaxf(a, 0.0f) * cw2[j];
    __syncthreads();
    if (j == 0) {
        float s = cb2[0];
        #pragma unroll
        for (int k = 0; k < 96; ++k) s += hid[k];
        out[g] = s;
    }
}

// ---------------- launch --------------------------------------------------
extern "C" void kernel_launch(void* const* d_in, const int* in_sizes, int n_in,
                              void* d_out, int out_size) {
    const float* x      = (const float*)d_in[0];
    const int*   ei     = (const int*)  d_in[1];
    const int*   src    = ei;
    const int*   dst    = ei + N_EDGES;
    const int*   batch  = (const int*)  d_in[2];
    const float* pocket = (const float*)d_in[3];
    const float* W0 = (const float*)d_in[4];  const float* b0 = (const float*)d_in[5];
    const float* W1 = (const float*)d_in[6];  const float* b1 = (const float*)d_in[7];
    const float* W2 = (const float*)d_in[8];  const float* b2 = (const float*)d_in[9];
    const float* bn_gamma = (const float*)d_in[10];
    const float* bn_beta  = (const float*)d_in[11];
    const float* bn_mean  = (const float*)d_in[12];
    const float* bn_var   = (const float*)d_in[13];
    const float* pw1 = (const float*)d_in[14]; const float* pb1 = (const float*)d_in[15];
    const float* pw2 = (const float*)d_in[16]; const float* pb2 = (const float*)d_in[17];
    const float* cw1 = (const float*)d_in[18]; const float* cb1 = (const float*)d_in[19];
    const float* cw2 = (const float*)d_in[20]; const float* cb2 = (const float*)d_in[21];
    float* out = (float*)d_out;

    // prep
    k_bnprep<<<1, 3 * HID>>>(bn_gamma, bn_beta, bn_mean, bn_var);
    k_deg_init <<<(N_NODES + 255) / 256, 256>>>();
    k_deg_count<<<(N_EDGES + 255) / 256, 256>>>(dst);
    k_deg_rsqrt<<<(N_NODES + 255) / 256, 256>>>();
    k_zero_pool<<<(N_GRAPHS * HID + N_GRAPHS + 255) / 256, 256>>>();
    k_pocket<<<1, 64>>>(pocket, pw1, pb1, pw2, pb2);

    int gemm_grid = (N_NODES + 63) / 64;
    int node_warp_grid = (N_NODES + 7) / 8;
    int edge_grid = (N_EDGES + 7) / 8;

    // layer 0
    k_gemm0<<<node_warp_grid, 256>>>(x, W0, b0);
    k_scatter<<<edge_grid, 256>>>(src, dst);
    // layer 1 (BN0+ReLU fused on A-load)
    k_gemm128<<<gemm_grid, 256>>>(W1, b1, 0);
    k_scatter<<<edge_grid, 256>>>(src, dst);
    // layer 2 (BN1+ReLU fused on A-load)
    k_gemm128<<<gemm_grid, 256>>>(W2, b2, 1);
    k_scatter<<<edge_grid, 256>>>(src, dst);

    // pooling (BN2+ReLU fused) + head
    k_pool<<<node_warp_grid, 256>>>(batch);
    k_head<<<N_GRAPHS, 96>>>(cw1, cb1, cw2, cb2, out);
}

// round 8
// speedup vs baseline: 1.3320x; 1.3320x over previous
#include <cuda_runtime.h>
#include <cuda_bf16.h>

#define N_NODES  100000
#define N_EDGES  600000
#define N_GRAPHS 256
#define HID      128
#define IN_DIM   7
#define BN_EPS   1e-5f
#define NB_SCAN  ((N_NODES + 255) / 256)   // 391 scan blocks

// ---------------- scratch (static device globals; no allocs allowed) --------
__device__ float g_buf0[N_NODES * HID];   // agg buffer (gather output)
__device__ float g_buf1[N_NODES * HID];   // hl buffer (GEMM output)
__device__ float g_dinv[N_NODES];         // rsqrt(deg+1)
__device__ float g_pool[N_GRAPHS * HID];
__device__ float g_cnt[N_GRAPHS];
__device__ float g_p[64];                 // pocket embedding
__device__ float g_bns[3][HID];           // BN scale  = gamma * rsqrt(var+eps)
__device__ float g_bnb[3][HID];           // BN shift  = beta - mean*scale
// CSR scratch
__device__ int   g_cnti[NB_SCAN * 256];   // per-node in-degree, then fill cursor
__device__ int   g_rowptr[N_NODES + 1];
__device__ int   g_ecol[N_EDGES];         // src node per CSR slot
__device__ int   g_bsum[512];             // per-block scan sums

// ---------------- tiny prep kernels ----------------------------------------
__global__ void k_bnprep(const float* __restrict__ gamma, const float* __restrict__ beta,
                         const float* __restrict__ mean,  const float* __restrict__ var) {
    int t = threadIdx.x;
    if (t < 3 * HID) {
        float s = gamma[t] * rsqrtf(var[t] + BN_EPS);
        ((float*)g_bns)[t] = s;
        ((float*)g_bnb)[t] = beta[t] - mean[t] * s;
    }
}

__global__ void k_zero_misc() {
    int i = blockIdx.x * blockDim.x + threadIdx.x;
    if (i < NB_SCAN * 256) g_cnti[i] = 0;
    if (i < N_GRAPHS * HID) g_pool[i] = 0.0f;
    if (i < N_GRAPHS) g_cnt[i] = 0.0f;
}

__global__ void k_count(const int* __restrict__ dst) {
    int i = blockIdx.x * blockDim.x + threadIdx.x;
    if (i < N_EDGES) atomicAdd(&g_cnti[dst[i]], 1);
}

__global__ void k_deg() {
    int i = blockIdx.x * blockDim.x + threadIdx.x;
    if (i < N_NODES) g_dinv[i] = rsqrtf((float)g_cnti[i] + 1.0f);  // +1 self-loop
}

// per-block inclusive scan of g_cnti -> g_rowptr (block-local), block totals -> g_bsum
__global__ void k_scan1() {
    __shared__ int s[256];
    int t = threadIdx.x;
    int i = blockIdx.x * 256 + t;
    int v = (i < N_NODES) ? g_cnti[i] : 0;
    s[t] = v;
    __syncthreads();
    #pragma unroll
    for (int d = 1; d < 256; d <<= 1) {
        int x = (t >= d) ? s[t - d] : 0;
        __syncthreads();
        if (t >= d) s[t] += x;
        __syncthreads();
    }
    if (i <= N_NODES) g_rowptr[i] = s[t];     // inclusive, block-local
    if (t == 255) g_bsum[blockIdx.x] = s[255];
}

// exclusive scan of the 391 block sums (one block of 512)
__global__ void k_scan2() {
    __shared__ int s[512];
    int t = threadIdx.x;
    int v = (t < NB_SCAN) ? g_bsum[t] : 0;
    s[t] = v;
    __syncthreads();
    #pragma unroll
    for (int d = 1; d < 512; d <<= 1) {
        int x = (t >= d) ? s[t - d] : 0;
        __syncthreads();
        if (t >= d) s[t] += x;
        __syncthreads();
    }
    if (t < NB_SCAN) g_bsum[t] = s[t] - v;    // exclusive block offset
}

// finalize exclusive rowptr, zero cursors
__global__ void k_scan3() {
    int i = blockIdx.x * blockDim.x + threadIdx.x;
    if (i < N_NODES) {
        int incl = g_rowptr[i];
        int cnt  = g_cnti[i];
        g_rowptr[i] = g_bsum[i >> 8] + incl - cnt;   // global exclusive
        g_cnti[i] = 0;
    }
    if (i == 0) g_rowptr[N_NODES] = N_EDGES;
}

__global__ void k_fill(const int* __restrict__ src, const int* __restrict__ dst) {
    int e = blockIdx.x * blockDim.x + threadIdx.x;
    if (e < N_EDGES) {
        int d = dst[e];
        int pos = g_rowptr[d] + atomicAdd(&g_cnti[d], 1);
        g_ecol[pos] = src[e];
    }
}

// pocket MLP: 28 -> 64 (relu) -> 64 ; one block of 64 threads
__global__ void k_pocket(const float* __restrict__ pocket,
                         const float* __restrict__ pw1, const float* __restrict__ pb1,
                         const float* __restrict__ pw2, const float* __restrict__ pb2) {
    __shared__ float t[64];
    int j = threadIdx.x;
    float a = pb1[j];
    #pragma unroll
    for (int k = 0; k < 28; ++k) a = fmaf(pocket[k], pw1[k * 64 + j], a);
    t[j] = fmaxf(a, 0.0f);
    __syncthreads();
    float b = pb2[j];
    #pragma unroll
    for (int k = 0; k < 64; ++k) b = fmaf(t[k], pw2[k * 64 + j], b);
    g_p[j] = b;
}

// ---------------- layer 0 GEMM: x[N,7] @ W0[7,128] -> g_buf1 (hl only) ------
__global__ void k_gemm0(const float* __restrict__ x, const float* __restrict__ W0) {
    __shared__ float Ws[IN_DIM * HID];
    int tid = threadIdx.x;
    for (int i = tid; i < IN_DIM * HID; i += 256) Ws[i] = W0[i];
    __syncthreads();

    int node = blockIdx.x * 8 + (tid >> 5);
    int col  = (tid & 31) * 4;
    if (node >= N_NODES) return;

    float xr[IN_DIM];
    #pragma unroll
    for (int i = 0; i < IN_DIM; ++i) xr[i] = __ldg(&x[node * IN_DIM + i]);

    float4 acc = make_float4(0.f, 0.f, 0.f, 0.f);
    #pragma unroll
    for (int i = 0; i < IN_DIM; ++i) {
        float4 w = *(const float4*)&Ws[i * HID + col];
        acc.x = fmaf(xr[i], w.x, acc.x);
        acc.y = fmaf(xr[i], w.y, acc.y);
        acc.z = fmaf(xr[i], w.z, acc.z);
        acc.w = fmaf(xr[i], w.w, acc.w);
    }
    *(float4*)(g_buf1 + node * HID + col) = acc;
}

// ---------------- 128-col SIMT GEMM with fused BN+ReLU on A-load -------------
// A = g_buf0 (raw agg), BN[bn_layer]+ReLU applied on load. Writes hl -> g_buf1.
__global__ void __launch_bounds__(256, 4)
k_gemm128(const float* __restrict__ W, int bn_layer) {
    __shared__ float As[16][68];
    __shared__ float Bs[16][128];

    int row0 = blockIdx.x * 64;
    int tid = threadIdx.x;
    int tx = tid & 31;         // 32 column-groups of 4
    int ty = tid >> 5;         // 8 row-groups of 8

    float acc[8][4];
    #pragma unroll
    for (int r = 0; r < 8; ++r)
        #pragma unroll
        for (int c = 0; c < 4; ++c) acc[r][c] = 0.f;

    const float* bns = g_bns[bn_layer];
    const float* bnb = g_bnb[bn_layer];

    for (int k0 = 0; k0 < HID; k0 += 16) {
        const float4* Wv = (const float4*)(W + k0 * HID);
        ((float4*)&Bs[0][0])[tid]       = Wv[tid];
        ((float4*)&Bs[0][0])[tid + 256] = Wv[tid + 256];

        int m  = tid >> 2;
        int kg = (tid & 3) * 4;
        int row = row0 + m;
        float4 a4 = make_float4(0.f, 0.f, 0.f, 0.f);
        if (row < N_NODES) a4 = *(const float4*)(g_buf0 + row * HID + k0 + kg);
        int kgl = k0 + kg;
        As[kg + 0][m] = fmaxf(fmaf(a4.x, bns[kgl + 0], bnb[kgl + 0]), 0.f);
        As[kg + 1][m] = fmaxf(fmaf(a4.y, bns[kgl + 1], bnb[kgl + 1]), 0.f);
        As[kg + 2][m] = fmaxf(fmaf(a4.z, bns[kgl + 2], bnb[kgl + 2]), 0.f);
        As[kg + 3][m] = fmaxf(fmaf(a4.w, bns[kgl + 3], bnb[kgl + 3]), 0.f);
        __syncthreads();

        #pragma unroll
        for (int kk = 0; kk < 16; ++kk) {
            float4 b  = *(const float4*)&Bs[kk][tx * 4];
            float4 a0 = *(const float4*)&As[kk][ty * 8];
            float4 a1 = *(const float4*)&As[kk][ty * 8 + 4];
            float a[8] = {a0.x, a0.y, a0.z, a0.w, a1.x, a1.y, a1.z, a1.w};
            #pragma unroll
            for (int r = 0; r < 8; ++r) {
                acc[r][0] = fmaf(a[r], b.x, acc[r][0]);
                acc[r][1] = fmaf(a[r], b.y, acc[r][1]);
                acc[r][2] = fmaf(a[r], b.z, acc[r][2]);
                acc[r][3] = fmaf(a[r], b.w, acc[r][3]);
            }
        }
        __syncthreads();
    }

    int col = tx * 4;
    #pragma unroll
    for (int r = 0; r < 8; ++r) {
        int row = row0 + ty * 8 + r;
        if (row >= N_NODES) break;
        *(float4*)(g_buf1 + row * HID + col) =
            make_float4(acc[r][0], acc[r][1], acc[r][2], acc[r][3]);
    }
}

// ---------------- CSR gather: agg[d] = (sum hl[s]*dinv[s] + hl[d]*dinv[d])*dinv[d] + b
// one warp per node, float4 lanes. Replaces atomic scatter AND GEMM epilogue.
__global__ void k_gather(const float* __restrict__ bias) {
    int node = blockIdx.x * 8 + (threadIdx.x >> 5);
    if (node >= N_NODES) return;
    int l = threadIdx.x & 31;

    int beg = g_rowptr[node];
    int end = g_rowptr[node + 1];

    float4 acc = make_float4(0.f, 0.f, 0.f, 0.f);
    for (int e = beg; e < end; ++e) {
        int s = g_ecol[e];                       // uniform per warp -> broadcast
        float ds = g_dinv[s];
        float4 v = ((const float4*)g_buf1)[s * 32 + l];
        acc.x = fmaf(v.x, ds, acc.x);
        acc.y = fmaf(v.y, ds, acc.y);
        acc.z = fmaf(v.z, ds, acc.z);
        acc.w = fmaf(v.w, ds, acc.w);
    }
    float dd = g_dinv[node];
    float4 hv = ((const float4*)g_buf1)[node * 32 + l];   // self-loop term
    acc.x = fmaf(hv.x, dd, acc.x);
    acc.y = fmaf(hv.y, dd, acc.y);
    acc.z = fmaf(hv.z, dd, acc.z);
    acc.w = fmaf(hv.w, dd, acc.w);
    float4 b4 = ((const float4*)bias)[l];
    float4 r = make_float4(fmaf(acc.x, dd, b4.x), fmaf(acc.y, dd, b4.y),
                           fmaf(acc.z, dd, b4.z), fmaf(acc.w, dd, b4.w));
    ((float4*)g_buf0)[node * 32 + l] = r;
}

// ---------------- pooling: BN2+ReLU then segment-sum per graph --------------
__global__ void k_pool(const int* __restrict__ batch) {
    int node = blockIdx.x * 8 + (threadIdx.x >> 5);
    if (node >= N_NODES) return;
    int l = threadIdx.x & 31;
    int b = batch[node];
    float4 v  = ((const float4*)g_buf0)[node * 32 + l];
    float4 sc = ((const float4*)g_bns[2])[l];
    float4 sh = ((const float4*)g_bnb[2])[l];
    v.x = fmaxf(fmaf(v.x, sc.x, sh.x), 0.f);
    v.y = fmaxf(fmaf(v.y, sc.y, sh.y), 0.f);
    v.z = fmaxf(fmaf(v.z, sc.z, sh.z), 0.f);
    v.w = fmaxf(fmaf(v.w, sc.w, sh.w), 0.f);
    float* p = g_pool + b * HID + l * 4;
    asm volatile("red.global.add.v4.f32 [%0], {%1, %2, %3, %4};"
                 :: "l"(p), "f"(v.x), "f"(v.y), "f"(v.z), "f"(v.w) : "memory");
    if (l == 0) atomicAdd(&g_cnt[b], 1.0f);
}

// ---------------- head: mean, concat pocket, 192->96 relu ->1 ---------------
__global__ void k_head(const float* __restrict__ cw1, const float* __restrict__ cb1,
                       const float* __restrict__ cw2, const float* __restrict__ cb2,
                       float* __restrict__ out) {
    __shared__ float emb[192];
    __shared__ float hid[96];
    int g = blockIdx.x;
    int j = threadIdx.x;
    float inv = 1.0f / fmaxf(g_cnt[g], 1.0f);
    for (int idx = j; idx < 192; idx += 96)
        emb[idx] = (idx < HID) ? g_pool[g * HID + idx] * inv : g_p[idx - HID];
    __syncthreads();
    float a = cb1[j];
    #pragma unroll 8
    for (int k = 0; k < 192; ++k) a = fmaf(emb[k], cw1[k * 96 + j], a);
    hid[j] = fmaxf(a, 0.0f) * cw2[j];
    __syncthreads();
    if (j == 0) {
        float s = cb2[0];
        #pragma unroll
        for (int k = 0; k < 96; ++k) s += hid[k];
        out[g] = s;
    }
}

// ---------------- launch --------------------------------------------------
extern "C" void kernel_launch(void* const* d_in, const int* in_sizes, int n_in,
                              void* d_out, int out_size) {
    const float* x      = (const float*)d_in[0];
    const int*   ei     = (const int*)  d_in[1];
    const int*   src    = ei;
    const int*   dst    = ei + N_EDGES;
    const int*   batch  = (const int*)  d_in[2];
    const float* pocket = (const float*)d_in[3];
    const float* W0 = (const float*)d_in[4];  const float* b0 = (const float*)d_in[5];
    const float* W1 = (const float*)d_in[6];  const float* b1 = (const float*)d_in[7];
    const float* W2 = (const float*)d_in[8];  const float* b2 = (const float*)d_in[9];
    const float* bn_gamma = (const float*)d_in[10];
    const float* bn_beta  = (const float*)d_in[11];
    const float* bn_mean  = (const float*)d_in[12];
    const float* bn_var   = (const float*)d_in[13];
    const float* pw1 = (const float*)d_in[14]; const float* pb1 = (const float*)d_in[15];
    const float* pw2 = (const float*)d_in[16]; const float* pb2 = (const float*)d_in[17];
    const float* cw1 = (const float*)d_in[18]; const float* cb1 = (const float*)d_in[19];
    const float* cw2 = (const float*)d_in[20]; const float* cb2 = (const float*)d_in[21];
    float* out = (float*)d_out;

    int nthr = (NB_SCAN * 256 > N_GRAPHS * HID) ? NB_SCAN * 256 : N_GRAPHS * HID;

    // prep + CSR build
    k_bnprep<<<1, 3 * HID>>>(bn_gamma, bn_beta, bn_mean, bn_var);
    k_zero_misc<<<(nthr + 255) / 256, 256>>>();
    k_count<<<(N_EDGES + 255) / 256, 256>>>(dst);
    k_deg<<<NB_SCAN, 256>>>();
    k_scan1<<<NB_SCAN, 256>>>();
    k_scan2<<<1, 512>>>();
    k_scan3<<<NB_SCAN, 256>>>();
    k_fill<<<(N_EDGES + 255) / 256, 256>>>(src, dst);
    k_pocket<<<1, 64>>>(pocket, pw1, pb1, pw2, pb2);

    int gemm_grid = (N_NODES + 63) / 64;
    int node_warp_grid = (N_NODES + 7) / 8;

    // layer 0
    k_gemm0<<<node_warp_grid, 256>>>(x, W0);
    k_gather<<<node_warp_grid, 256>>>(b0);
    // layer 1 (BN0+ReLU fused on A-load)
    k_gemm128<<<gemm_grid, 256>>>(W1, 0);
    k_gather<<<node_warp_grid, 256>>>(b1);
    // layer 2 (BN1+ReLU fused on A-load)
    k_gemm128<<<gemm_grid, 256>>>(W2, 1);
    k_gather<<<node_warp_grid, 256>>>(b2);

    // pooling (BN2+ReLU fused) + head
    k_pool<<<node_warp_grid, 256>>>(batch);
    k_head<<<N_GRAPHS, 96>>>(cw1, cb1, cw2, cb2, out);
}

// round 10
// speedup vs baseline: 1.5220x; 1.1426x over previous
#include <cuda_runtime.h>
#include <cuda_bf16.h>
#include <mma.h>

using namespace nvcuda;

#define N_NODES  100000
#define N_EDGES  600000
#define N_GRAPHS 256
#define HID      128
#define IN_DIM   7
#define BN_EPS   1e-5f
#define NB_SCAN  ((N_NODES + 255) / 256)   // 391 scan blocks
#define N_PAD    (N_NODES + 128)           // row padding for full-tile wmma I/O

// ---------------- scratch (static device globals; no allocs allowed) --------
__device__ float g_buf0[N_PAD * HID];     // agg buffer (gather output)
__device__ float g_buf1[N_PAD * HID];     // hl buffer (GEMM output)
__device__ float g_dinv[N_NODES];         // rsqrt(deg+1)
__device__ float g_pool[N_GRAPHS * HID];
__device__ float g_cnt[N_GRAPHS];
__device__ float g_p[64];                 // pocket embedding
__device__ float g_bns[3][HID];           // BN scale  = gamma * rsqrt(var+eps)
__device__ float g_bnb[3][HID];           // BN shift  = beta - mean*scale
// CSR scratch
__device__ int   g_cnti[NB_SCAN * 256];   // per-node in-degree, then fill cursor
__device__ int   g_rowptr[N_NODES + 1];
__device__ int   g_ecol[N_EDGES];         // src node per CSR slot
__device__ int   g_bsum[512];             // per-block scan sums

// ---------------- tiny prep kernels ----------------------------------------
__global__ void k_bnprep(const float* __restrict__ gamma, const float* __restrict__ beta,
                         const float* __restrict__ mean,  const float* __restrict__ var) {
    int t = threadIdx.x;
    if (t < 3 * HID) {
        float s = gamma[t] * rsqrtf(var[t] + BN_EPS);
        ((float*)g_bns)[t] = s;
        ((float*)g_bnb)[t] = beta[t] - mean[t] * s;
    }
}

__global__ void k_zero_misc() {
    int i = blockIdx.x * blockDim.x + threadIdx.x;
    if (i < NB_SCAN * 256) g_cnti[i] = 0;
    if (i < N_GRAPHS * HID) g_pool[i] = 0.0f;
    if (i < N_GRAPHS) g_cnt[i] = 0.0f;
}

__global__ void k_count(const int* __restrict__ dst) {
    int i = blockIdx.x * blockDim.x + threadIdx.x;
    if (i < N_EDGES) atomicAdd(&g_cnti[dst[i]], 1);
}

__global__ void k_deg() {
    int i = blockIdx.x * blockDim.x + threadIdx.x;
    if (i < N_NODES) g_dinv[i] = rsqrtf((float)g_cnti[i] + 1.0f);  // +1 self-loop
}

// per-block inclusive scan of g_cnti -> g_rowptr (block-local), block totals -> g_bsum
__global__ void k_scan1() {
    __shared__ int s[256];
    int t = threadIdx.x;
    int i = blockIdx.x * 256 + t;
    int v = (i < N_NODES) ? g_cnti[i] : 0;
    s[t] = v;
    __syncthreads();
    #pragma unroll
    for (int d = 1; d < 256; d <<= 1) {
        int x = (t >= d) ? s[t - d] : 0;
        __syncthreads();
        if (t >= d) s[t] += x;
        __syncthreads();
    }
    if (i <= N_NODES) g_rowptr[i] = s[t];     // inclusive, block-local
    if (t == 255) g_bsum[blockIdx.x] = s[255];
}

// exclusive scan of the 391 block sums (one block of 512)
__global__ void k_scan2() {
    __shared__ int s[512];
    int t = threadIdx.x;
    int v = (t < NB_SCAN) ? g_bsum[t] : 0;
    s[t] = v;
    __syncthreads();
    #pragma unroll
    for (int d = 1; d < 512; d <<= 1) {
        int x = (t >= d) ? s[t - d] : 0;
        __syncthreads();
        if (t >= d) s[t] += x;
        __syncthreads();
    }
    if (t < NB_SCAN) g_bsum[t] = s[t] - v;    // exclusive block offset
}

// finalize exclusive rowptr, zero cursors
__global__ void k_scan3() {
    int i = blockIdx.x * blockDim.x + threadIdx.x;
    if (i < N_NODES) {
        int incl = g_rowptr[i];
        int cnt  = g_cnti[i];
        g_rowptr[i] = g_bsum[i >> 8] + incl - cnt;   // global exclusive
        g_cnti[i] = 0;
    }
    if (i == 0) g_rowptr[N_NODES] = N_EDGES;
}

__global__ void k_fill(const int* __restrict__ src, const int* __restrict__ dst) {
    int e = blockIdx.x * blockDim.x + threadIdx.x;
    if (e < N_EDGES) {
        int d = dst[e];
        int pos = g_rowptr[d] + atomicAdd(&g_cnti[d], 1);
        g_ecol[pos] = src[e];
    }
}

// pocket MLP: 28 -> 64 (relu) -> 64 ; one block of 64 threads
__global__ void k_pocket(const float* __restrict__ pocket,
                         const float* __restrict__ pw1, const float* __restrict__ pb1,
                         const float* __restrict__ pw2, const float* __restrict__ pb2) {
    __shared__ float t[64];
    int j = threadIdx.x;
    float a = pb1[j];
    #pragma unroll
    for (int k = 0; k < 28; ++k) a = fmaf(pocket[k], pw1[k * 64 + j], a);
    t[j] = fmaxf(a, 0.0f);
    __syncthreads();
    float b = pb2[j];
    #pragma unroll
    for (int k = 0; k < 64; ++k) b = fmaf(t[k], pw2[k * 64 + j], b);
    g_p[j] = b;
}

// ---------------- layer 0 GEMM: x[N,7] @ W0[7,128] -> g_buf1 (hl only) ------
__global__ void k_gemm0(const float* __restrict__ x, const float* __restrict__ W0) {
    __shared__ float Ws[IN_DIM * HID];
    int tid = threadIdx.x;
    for (int i = tid; i < IN_DIM * HID; i += 256) Ws[i] = W0[i];
    __syncthreads();

    int node = blockIdx.x * 8 + (tid >> 5);
    int col  = (tid & 31) * 4;
    if (node >= N_NODES) return;

    float xr[IN_DIM];
    #pragma unroll
    for (int i = 0; i < IN_DIM; ++i) xr[i] = __ldg(&x[node * IN_DIM + i]);

    float4 acc = make_float4(0.f, 0.f, 0.f, 0.f);
    #pragma unroll
    for (int i = 0; i < IN_DIM; ++i) {
        float4 w = *(const float4*)&Ws[i * HID + col];
        acc.x = fmaf(xr[i], w.x, acc.x);
        acc.y = fmaf(xr[i], w.y, acc.y);
        acc.z = fmaf(xr[i], w.z, acc.z);
        acc.w = fmaf(xr[i], w.w, acc.w);
    }
    *(float4*)(g_buf1 + node * HID + col) = acc;
}

// ---------------- wmma tf32 GEMM: 128x128 tile, BN+ReLU fused on A-load -----
// A = g_buf0 (raw agg), BN[bn_layer]+ReLU on load. Writes hl -> g_buf1.
// 8 warps: warp_m = wid>>1 (4 x 32 rows), warp_n = wid&1 (2 x 64 cols).
// Buffers padded to N_PAD rows so full 128-row tiles load/store unconditionally.
__global__ void __launch_bounds__(256, 2)
k_gemm128_tc(const float* __restrict__ W, int bn_layer) {
    __shared__ float As[128][36];    // [m][k] tf32-converted, ld=36 (mult of 4)
    __shared__ float Bs[32][132];    // [k][n] tf32-converted, ld=132 (mult of 4)

    int tid = threadIdx.x;
    int wid = tid >> 5;
    int warp_m = wid >> 1, warp_n = wid & 1;
    int row0 = blockIdx.x * 128;

    const float* bns = g_bns[bn_layer];
    const float* bnb = g_bnb[bn_layer];

    wmma::fragment<wmma::accumulator, 16, 16, 8, float> acc[2][4];
    #pragma unroll
    for (int mt = 0; mt < 2; ++mt)
        #pragma unroll
        for (int nt = 0; nt < 4; ++nt) wmma::fill_fragment(acc[mt][nt], 0.0f);

    for (int k0 = 0; k0 < HID; k0 += 32) {
        // B chunk 32x128 -> Bs (tf32-converted)
        #pragma unroll
        for (int i = 0; i < 4; ++i) {
            int f = tid + 256 * i;
            int r = f >> 5, c = (f & 31) * 4;
            float4 w = *(const float4*)(W + (k0 + r) * HID + c);
            Bs[r][c + 0] = wmma::__float_to_tf32(w.x);
            Bs[r][c + 1] = wmma::__float_to_tf32(w.y);
            Bs[r][c + 2] = wmma::__float_to_tf32(w.z);
            Bs[r][c + 3] = wmma::__float_to_tf32(w.w);
        }
        // A chunk 128x32 with BN+ReLU fused -> As (tf32-converted)
        #pragma unroll
        for (int i = 0; i < 4; ++i) {
            int f = tid + 256 * i;
            int r = f >> 3, c4 = (f & 7) * 4;
            float4 a = *(const float4*)(g_buf0 + (row0 + r) * HID + k0 + c4);
            int kg = k0 + c4;
            As[r][c4 + 0] = wmma::__float_to_tf32(fmaxf(fmaf(a.x, bns[kg + 0], bnb[kg + 0]), 0.f));
            As[r][c4 + 1] = wmma::__float_to_tf32(fmaxf(fmaf(a.y, bns[kg + 1], bnb[kg + 1]), 0.f));
            As[r][c4 + 2] = wmma::__float_to_tf32(fmaxf(fmaf(a.z, bns[kg + 2], bnb[kg + 2]), 0.f));
            As[r][c4 + 3] = wmma::__float_to_tf32(fmaxf(fmaf(a.w, bns[kg + 3], bnb[kg + 3]), 0.f));
        }
        __syncthreads();

        #pragma unroll
        for (int kk = 0; kk < 4; ++kk) {
            wmma::fragment<wmma::matrix_a, 16, 16, 8, wmma::precision::tf32, wmma::row_major> fa[2];
            #pragma unroll
            for (int mt = 0; mt < 2; ++mt)
                wmma::load_matrix_sync(fa[mt], &As[warp_m * 32 + mt * 16][kk * 8], 36);
            #pragma unroll
            for (int nt = 0; nt < 4; ++nt) {
                wmma::fragment<wmma::matrix_b, 16, 16, 8, wmma::precision::tf32, wmma::row_major> fb;
                wmma::load_matrix_sync(fb, &Bs[kk * 8][warp_n * 64 + nt * 16], 132);
                wmma::mma_sync(acc[0][nt], fa[0], fb, acc[0][nt]);
                wmma::mma_sync(acc[1][nt], fa[1], fb, acc[1][nt]);
            }
        }
        __syncthreads();
    }

    #pragma unroll
    for (int mt = 0; mt < 2; ++mt) {
        int row = row0 + warp_m * 32 + mt * 16;
        #pragma unroll
        for (int nt = 0; nt < 4; ++nt) {
            int col = warp_n * 64 + nt * 16;
            wmma::store_matrix_sync(g_buf1 + row * HID + col, acc[mt][nt], HID, wmma::mem_row_major);
        }
    }
}

// ---------------- CSR gather: agg[d] = (sum hl[s]*dinv[s] + hl[d]*dinv[d])*dinv[d] + b
// one warp per node, float4 lanes. Replaces atomic scatter AND GEMM epilogue.
__global__ void k_gather(const float* __restrict__ bias) {
    int node = blockIdx.x * 8 + (threadIdx.x >> 5);
    if (node >= N_NODES) return;
    int l = threadIdx.x & 31;

    int beg = g_rowptr[node];
    int end = g_rowptr[node + 1];

    float4 acc = make_float4(0.f, 0.f, 0.f, 0.f);
    for (int e = beg; e < end; ++e) {
        int s = g_ecol[e];                       // uniform per warp -> broadcast
        float ds = g_dinv[s];
        float4 v = ((const float4*)g_buf1)[s * 32 + l];
        acc.x = fmaf(v.x, ds, acc.x);
        acc.y = fmaf(v.y, ds, acc.y);
        acc.z = fmaf(v.z, ds, acc.z);
        acc.w = fmaf(v.w, ds, acc.w);
    }
    float dd = g_dinv[node];
    float4 hv = ((const float4*)g_buf1)[node * 32 + l];   // self-loop term
    acc.x = fmaf(hv.x, dd, acc.x);
    acc.y = fmaf(hv.y, dd, acc.y);
    acc.z = fmaf(hv.z, dd, acc.z);
    acc.w = fmaf(hv.w, dd, acc.w);
    float4 b4 = ((const float4*)bias)[l];
    float4 r = make_float4(fmaf(acc.x, dd, b4.x), fmaf(acc.y, dd, b4.y),
                           fmaf(acc.z, dd, b4.z), fmaf(acc.w, dd, b4.w));
    ((float4*)g_buf0)[node * 32 + l] = r;
}

// ---------------- pooling: BN2+ReLU then segment-sum per graph --------------
__global__ void k_pool(const int* __restrict__ batch) {
    int node = blockIdx.x * 8 + (threadIdx.x >> 5);
    if (node >= N_NODES) return;
    int l = threadIdx.x & 31;
    int b = batch[node];
    float4 v  = ((const float4*)g_buf0)[node * 32 + l];
    float4 sc = ((const float4*)g_bns[2])[l];
    float4 sh = ((const float4*)g_bnb[2])[l];
    v.x = fmaxf(fmaf(v.x, sc.x, sh.x), 0.f);
    v.y = fmaxf(fmaf(v.y, sc.y, sh.y), 0.f);
    v.z = fmaxf(fmaf(v.z, sc.z, sh.z), 0.f);
    v.w = fmaxf(fmaf(v.w, sc.w, sh.w), 0.f);
    float* p = g_pool + b * HID + l * 4;
    asm volatile("red.global.add.v4.f32 [%0], {%1, %2, %3, %4};"
                 :: "l"(p), "f"(v.x), "f"(v.y), "f"(v.z), "f"(v.w) : "memory");
    if (l == 0) atomicAdd(&g_cnt[b], 1.0f);
}

// ---------------- head: mean, concat pocket, 192->96 relu ->1 ---------------
__global__ void k_head(const float* __restrict__ cw1, const float* __restrict__ cb1,
                       const float* __restrict__ cw2, const float* __restrict__ cb2,
                       float* __restrict__ out) {
    __shared__ float emb[192];
    __shared__ float hid[96];
    int g = blockIdx.x;
    int j = threadIdx.x;
    float inv = 1.0f / fmaxf(g_cnt[g], 1.0f);
    for (int idx = j; idx < 192; idx += 96)
        emb[idx] = (idx < HID) ? g_pool[g * HID + idx] * inv : g_p[idx - HID];
    __syncthreads();
    float a = cb1[j];
    #pragma unroll 8
    for (int k = 0; k < 192; ++k) a = fmaf(emb[k], cw1[k * 96 + j], a);
    hid[j] = fmaxf(a, 0.0f) * cw2[j];
    __syncthreads();
    if (j == 0) {
        float s = cb2[0];
        #pragma unroll
        for (int k = 0; k < 96; ++k) s += hid[k];
        out[g] = s;
    }
}

// ---------------- launch --------------------------------------------------
extern "C" void kernel_launch(void* const* d_in, const int* in_sizes, int n_in,
                              void* d_out, int out_size) {
    const float* x      = (const float*)d_in[0];
    const int*   ei     = (const int*)  d_in[1];
    const int*   src    = ei;
    const int*   dst    = ei + N_EDGES;
    const int*   batch  = (const int*)  d_in[2];
    const float* pocket = (const float*)d_in[3];
    const float* W0 = (const float*)d_in[4];  const float* b0 = (const float*)d_in[5];
    const float* W1 = (const float*)d_in[6];  const float* b1 = (const float*)d_in[7];
    const float* W2 = (const float*)d_in[8];  const float* b2 = (const float*)d_in[9];
    const float* bn_gamma = (const float*)d_in[10];
    const float* bn_beta  = (const float*)d_in[11];
    const float* bn_mean  = (const float*)d_in[12];
    const float* bn_var   = (const float*)d_in[13];
    const float* pw1 = (const float*)d_in[14]; const float* pb1 = (const float*)d_in[15];
    const float* pw2 = (const float*)d_in[16]; const float* pb2 = (const float*)d_in[17];
    const float* cw1 = (const float*)d_in[18]; const float* cb1 = (const float*)d_in[19];
    const float* cw2 = (const float*)d_in[20]; const float* cb2 = (const float*)d_in[21];
    float* out = (float*)d_out;

    int nthr = (NB_SCAN * 256 > N_GRAPHS * HID) ? NB_SCAN * 256 : N_GRAPHS * HID;

    // prep + CSR build
    k_bnprep<<<1, 3 * HID>>>(bn_gamma, bn_beta, bn_mean, bn_var);
    k_zero_misc<<<(nthr + 255) / 256, 256>>>();
    k_count<<<(N_EDGES + 255) / 256, 256>>>(dst);
    k_deg<<<NB_SCAN, 256>>>();
    k_scan1<<<NB_SCAN, 256>>>();
    k_scan2<<<1, 512>>>();
    k_scan3<<<NB_SCAN, 256>>>();
    k_fill<<<(N_EDGES + 255) / 256, 256>>>(src, dst);
    k_pocket<<<1, 64>>>(pocket, pw1, pb1, pw2, pb2);

    int tc_grid = (N_NODES + 127) / 128;          // 782 full tiles (padded bufs)
    int node_warp_grid = (N_NODES + 7) / 8;

    // layer 0
    k_gemm0<<<node_warp_grid, 256>>>(x, W0);
    k_gather<<<node_warp_grid, 256>>>(b0);
    // layer 1 (BN0+ReLU fused on A-load)
    k_gemm128_tc<<<tc_grid, 256>>>(W1, 0);
    k_gather<<<node_warp_grid, 256>>>(b1);
    // layer 2 (BN1+ReLU fused on A-load)
    k_gemm128_tc<<<tc_grid, 256>>>(W2, 1);
    k_gather<<<node_warp_grid, 256>>>(b2);

    // pooling (BN2+ReLU fused) + head
    k_pool<<<node_warp_grid, 256>>>(batch);
    k_head<<<N_GRAPHS, 96>>>(cw1, cb1, cw2, cb2, out);
}

// round 12
// speedup vs baseline: 1.5527x; 1.0202x over previous
#include <cuda_runtime.h>
#include <cuda_bf16.h>
#include <mma.h>

using namespace nvcuda;

#define N_NODES  100000
#define N_EDGES  600000
#define N_GRAPHS 256
#define HID      128
#define IN_DIM   7
#define BN_EPS   1e-5f
#define NB_SCAN  ((N_NODES + 255) / 256)   // 391 scan blocks
#define N_PAD    (N_NODES + 128)           // row padding for full-tile wmma I/O

// ---------------- scratch (static device globals; no allocs allowed) --------
__device__ float g_buf0[N_PAD * HID];     // h buffer (gather output, post BN+ReLU)
__device__ float g_buf1[N_PAD * HID];     // hl buffer (GEMM output)
__device__ float g_Wc[2][HID * HID];      // tf32-rounded W1, W2
__device__ float g_dinv[N_NODES];         // rsqrt(deg+1)
__device__ float g_pool[N_GRAPHS * HID];
__device__ float g_cnt[N_GRAPHS];
__device__ float g_p[64];                 // pocket embedding
__device__ float g_bns[3][HID];           // BN scale  = gamma * rsqrt(var+eps)
__device__ float g_bnb[3][HID];           // BN shift  = beta - mean*scale
// CSR scratch
__device__ int   g_cnti[NB_SCAN * 256];   // per-node in-degree, then fill cursor
__device__ int   g_rowptr[N_NODES + 1];
__device__ int   g_ecol[N_EDGES];         // src node per CSR slot
__device__ int   g_bsum[512];             // per-block scan sums

// ---------------- merged prep: BN fold + pocket MLP (1 block, 384 thr) ------
__global__ void k_prep(const float* __restrict__ gamma, const float* __restrict__ beta,
                       const float* __restrict__ mean,  const float* __restrict__ var,
                       const float* __restrict__ pocket,
                       const float* __restrict__ pw1, const float* __restrict__ pb1,
                       const float* __restrict__ pw2, const float* __restrict__ pb2) {
    __shared__ float t[64];
    int j = threadIdx.x;
    if (j < 3 * HID) {
        float s = gamma[j] * rsqrtf(var[j] + BN_EPS);
        ((float*)g_bns)[j] = s;
        ((float*)g_bnb)[j] = beta[j] - mean[j] * s;
    }
    if (j < 64) {
        float a = pb1[j];
        #pragma unroll
        for (int k = 0; k < 28; ++k) a = fmaf(pocket[k], pw1[k * 64 + j], a);
        t[j] = fmaxf(a, 0.0f);
    }
    __syncthreads();
    if (j < 64) {
        float b = pb2[j];
        #pragma unroll
        for (int k = 0; k < 64; ++k) b = fmaf(t[k], pw2[k * 64 + j], b);
        g_p[j] = b;
    }
}

// tf32-round W1, W2 into g_Wc
__global__ void k_prepW(const float* __restrict__ W1, const float* __restrict__ W2) {
    int i = blockIdx.x * blockDim.x + threadIdx.x;
    if (i < HID * HID) {
        g_Wc[0][i] = wmma::__float_to_tf32(W1[i]);
        g_Wc[1][i] = wmma::__float_to_tf32(W2[i]);
    }
}

__global__ void k_zero_misc() {
    int i = blockIdx.x * blockDim.x + threadIdx.x;
    if (i < NB_SCAN * 256) g_cnti[i] = 0;
    if (i < N_GRAPHS * HID) g_pool[i] = 0.0f;
    if (i < N_GRAPHS) g_cnt[i] = 0.0f;
}

__global__ void k_count(const int* __restrict__ dst) {
    int i = blockIdx.x * blockDim.x + threadIdx.x;
    if (i < N_EDGES) atomicAdd(&g_cnti[dst[i]], 1);
}

// per-block inclusive scan of g_cnti -> g_rowptr (block-local), block totals -> g_bsum
// also computes dinv = rsqrt(deg+1)
__global__ void k_scan1() {
    __shared__ int s[256];
    int t = threadIdx.x;
    int i = blockIdx.x * 256 + t;
    int v = (i < N_NODES) ? g_cnti[i] : 0;
    if (i < N_NODES) g_dinv[i] = rsqrtf((float)v + 1.0f);
    s[t] = v;
    __syncthreads();
    #pragma unroll
    for (int d = 1; d < 256; d <<= 1) {
        int x = (t >= d) ? s[t - d] : 0;
        __syncthreads();
        if (t >= d) s[t] += x;
        __syncthreads();
    }
    if (i <= N_NODES) g_rowptr[i] = s[t];     // inclusive, block-local
    if (t == 255) g_bsum[blockIdx.x] = s[255];
}

// exclusive scan of the 391 block sums (one block of 512)
__global__ void k_scan2() {
    __shared__ int s[512];
    int t = threadIdx.x;
    int v = (t < NB_SCAN) ? g_bsum[t] : 0;
    s[t] = v;
    __syncthreads();
    #pragma unroll
    for (int d = 1; d < 512; d <<= 1) {
        int x = (t >= d) ? s[t - d] : 0;
        __syncthreads();
        if (t >= d) s[t] += x;
        __syncthreads();
    }
    if (t < NB_SCAN) g_bsum[t] = s[t] - v;    // exclusive block offset
}

// finalize exclusive rowptr, zero cursors
__global__ void k_scan3() {
    int i = blockIdx.x * blockDim.x + threadIdx.x;
    if (i < N_NODES) {
        int incl = g_rowptr[i];
        int cnt  = g_cnti[i];
        g_rowptr[i] = g_bsum[i >> 8] + incl - cnt;   // global exclusive
        g_cnti[i] = 0;
    }
    if (i == 0) g_rowptr[N_NODES] = N_EDGES;
}

__global__ void k_fill(const int* __restrict__ src, const int* __restrict__ dst) {
    int e = blockIdx.x * blockDim.x + threadIdx.x;
    if (e < N_EDGES) {
        int d = dst[e];
        int pos = g_rowptr[d] + atomicAdd(&g_cnti[d], 1);
        g_ecol[pos] = src[e];
    }
}

// ---------------- layer 0 GEMM: x[N,7] @ W0[7,128] -> g_buf1 (hl only) ------
__global__ void k_gemm0(const float* __restrict__ x, const float* __restrict__ W0) {
    __shared__ float Ws[IN_DIM * HID];
    int tid = threadIdx.x;
    for (int i = tid; i < IN_DIM * HID; i += 256) Ws[i] = W0[i];
    __syncthreads();

    int node = blockIdx.x * 8 + (tid >> 5);
    int col  = (tid & 31) * 4;
    if (node >= N_NODES) return;

    float xr[IN_DIM];
    #pragma unroll
    for (int i = 0; i < IN_DIM; ++i) xr[i] = __ldg(&x[node * IN_DIM + i]);

    float4 acc = make_float4(0.f, 0.f, 0.f, 0.f);
    #pragma unroll
    for (int i = 0; i < IN_DIM; ++i) {
        float4 w = *(const float4*)&Ws[i * HID + col];
        acc.x = fmaf(xr[i], w.x, acc.x);
        acc.y = fmaf(xr[i], w.y, acc.y);
        acc.z = fmaf(xr[i], w.z, acc.z);
        acc.w = fmaf(xr[i], w.w, acc.w);
    }
    *(float4*)(g_buf1 + node * HID + col) = acc;
}

// ---------------- wmma tf32 GEMM: 128x128 tile, PURE raw-copy + mma ---------
// A = g_buf0 (already BN+ReLU'd and tf32-rounded by gather), B = g_Wc[widx]
// (indexed in DEVICE code — device-global addresses are invalid as host-side
// kernel args). Writes hl -> g_buf1. Smem fills are plain float4 copies.
__global__ void __launch_bounds__(256, 2)
k_gemm128_tc(int widx) {
    __shared__ float As[128][36];    // [m][k], ld=36
    __shared__ float Bs[32][132];    // [k][n], ld=132

    const float* Wc = g_Wc[widx];
    int tid = threadIdx.x;
    int wid = tid >> 5;
    int warp_m = wid >> 1, warp_n = wid & 1;
    int row0 = blockIdx.x * 128;

    wmma::fragment<wmma::accumulator, 16, 16, 8, float> acc[2][4];
    #pragma unroll
    for (int mt = 0; mt < 2; ++mt)
        #pragma unroll
        for (int nt = 0; nt < 4; ++nt) wmma::fill_fragment(acc[mt][nt], 0.0f);

    for (int k0 = 0; k0 < HID; k0 += 32) {
        // B chunk 32x128 raw copy
        #pragma unroll
        for (int i = 0; i < 4; ++i) {
            int f = tid + 256 * i;
            int r = f >> 5, c = (f & 31) * 4;
            *(float4*)&Bs[r][c] = *(const float4*)(Wc + (k0 + r) * HID + c);
        }
        // A chunk 128x32 raw copy
        #pragma unroll
        for (int i = 0; i < 4; ++i) {
            int f = tid + 256 * i;
            int r = f >> 3, c4 = (f & 7) * 4;
            *(float4*)&As[r][c4] = *(const float4*)(g_buf0 + (row0 + r) * HID + k0 + c4);
        }
        __syncthreads();

        #pragma unroll
        for (int kk = 0; kk < 4; ++kk) {
            wmma::fragment<wmma::matrix_a, 16, 16, 8, wmma::precision::tf32, wmma::row_major> fa[2];
            #pragma unroll
            for (int mt = 0; mt < 2; ++mt)
                wmma::load_matrix_sync(fa[mt], &As[warp_m * 32 + mt * 16][kk * 8], 36);
            #pragma unroll
            for (int nt = 0; nt < 4; ++nt) {
                wmma::fragment<wmma::matrix_b, 16, 16, 8, wmma::precision::tf32, wmma::row_major> fb;
                wmma::load_matrix_sync(fb, &Bs[kk * 8][warp_n * 64 + nt * 16], 132);
                wmma::mma_sync(acc[0][nt], fa[0], fb, acc[0][nt]);
                wmma::mma_sync(acc[1][nt], fa[1], fb, acc[1][nt]);
            }
        }
        __syncthreads();
    }

    #pragma unroll
    for (int mt = 0; mt < 2; ++mt) {
        int row = row0 + warp_m * 32 + mt * 16;
        #pragma unroll
        for (int nt = 0; nt < 4; ++nt) {
            int col = warp_n * 64 + nt * 16;
            wmma::store_matrix_sync(g_buf1 + row * HID + col, acc[mt][nt], HID, wmma::mem_row_major);
        }
    }
}

// ---------------- CSR gather + full epilogue --------------------------------
// agg = (sum_s hl[s]*dinv[s] + hl[d]*dinv[d]) * dinv[d] + bias
// then h = relu(BN[bn_idx](agg)); if do_round, tf32-round (exact GEMM input).
__global__ void k_gather(const float* __restrict__ bias, int bn_idx, int do_round) {
    int node = blockIdx.x * 8 + (threadIdx.x >> 5);
    if (node >= N_NODES) return;
    int l = threadIdx.x & 31;

    int beg = g_rowptr[node];
    int end = g_rowptr[node + 1];

    float4 acc = make_float4(0.f, 0.f, 0.f, 0.f);
    for (int e = beg; e < end; ++e) {
        int s = g_ecol[e];                       // uniform per warp -> broadcast
        float ds = g_dinv[s];
        float4 v = ((const float4*)g_buf1)[s * 32 + l];
        acc.x = fmaf(v.x, ds, acc.x);
        acc.y = fmaf(v.y, ds, acc.y);
        acc.z = fmaf(v.z, ds, acc.z);
        acc.w = fmaf(v.w, ds, acc.w);
    }
    float dd = g_dinv[node];
    float4 hv = ((const float4*)g_buf1)[node * 32 + l];   // self-loop term
    acc.x = fmaf(hv.x, dd, acc.x);
    acc.y = fmaf(hv.y, dd, acc.y);
    acc.z = fmaf(hv.z, dd, acc.z);
    acc.w = fmaf(hv.w, dd, acc.w);
    float4 b4 = ((const float4*)bias)[l];
    float4 r = make_float4(fmaf(acc.x, dd, b4.x), fmaf(acc.y, dd, b4.y),
                           fmaf(acc.z, dd, b4.z), fmaf(acc.w, dd, b4.w));
    // BN + ReLU
    float4 sc = ((const float4*)g_bns[bn_idx])[l];
    float4 sh = ((const float4*)g_bnb[bn_idx])[l];
    r.x = fmaxf(fmaf(r.x, sc.x, sh.x), 0.f);
    r.y = fmaxf(fmaf(r.y, sc.y, sh.y), 0.f);
    r.z = fmaxf(fmaf(r.z, sc.z, sh.z), 0.f);
    r.w = fmaxf(fmaf(r.w, sc.w, sh.w), 0.f);
    if (do_round) {
        r.x = wmma::__float_to_tf32(r.x);
        r.y = wmma::__float_to_tf32(r.y);
        r.z = wmma::__float_to_tf32(r.z);
        r.w = wmma::__float_to_tf32(r.w);
    }
    ((float4*)g_buf0)[node * 32 + l] = r;
}

// ---------------- pooling: plain segment-sum (h already post BN+ReLU) -------
__global__ void k_pool(const int* __restrict__ batch) {
    int node = blockIdx.x * 8 + (threadIdx.x >> 5);
    if (node >= N_NODES) return;
    int l = threadIdx.x & 31;
    int b = batch[node];
    float4 v = ((const float4*)g_buf0)[node * 32 + l];
    float* p = g_pool + b * HID + l * 4;
    asm volatile("red.global.add.v4.f32 [%0], {%1, %2, %3, %4};"
                 :: "l"(p), "f"(v.x), "f"(v.y), "f"(v.z), "f"(v.w) : "memory");
    if (l == 0) atomicAdd(&g_cnt[b], 1.0f);
}

// ---------------- head: mean, concat pocket, 192->96 relu ->1 ---------------
__global__ void k_head(const float* __restrict__ cw1, const float* __restrict__ cb1,
                       const float* __restrict__ cw2, const float* __restrict__ cb2,
                       float* __restrict__ out) {
    __shared__ float emb[192];
    __shared__ float hid[96];
    int g = blockIdx.x;
    int j = threadIdx.x;
    float inv = 1.0f / fmaxf(g_cnt[g], 1.0f);
    for (int idx = j; idx < 192; idx += 96)
        emb[idx] = (idx < HID) ? g_pool[g * HID + idx] * inv : g_p[idx - HID];
    __syncthreads();
    float a = cb1[j];
    #pragma unroll 8
    for (int k = 0; k < 192; ++k) a = fmaf(emb[k], cw1[k * 96 + j], a);
    hid[j] = fmaxf(a, 0.0f) * cw2[j];
    __syncthreads();
    if (j == 0) {
        float s = cb2[0];
        #pragma unroll
        for (int k = 0; k < 96; ++k) s += hid[k];
        out[g] = s;
    }
}

// ---------------- launch --------------------------------------------------
extern "C" void kernel_launch(void* const* d_in, const int* in_sizes, int n_in,
                              void* d_out, int out_size) {
    const float* x      = (const float*)d_in[0];
    const int*   ei     = (const int*)  d_in[1];
    const int*   src    = ei;
    const int*   dst    = ei + N_EDGES;
    const int*   batch  = (const int*)  d_in[2];
    const float* pocket = (const float*)d_in[3];
    const float* W0 = (const float*)d_in[4];  const float* b0 = (const float*)d_in[5];
    const float* W1 = (const float*)d_in[6];  const float* b1 = (const float*)d_in[7];
    const float* W2 = (const float*)d_in[8];  const float* b2 = (const float*)d_in[9];
    const float* bn_gamma = (const float*)d_in[10];
    const float* bn_beta  = (const float*)d_in[11];
    const float* bn_mean  = (const float*)d_in[12];
    const float* bn_var   = (const float*)d_in[13];
    const float* pw1 = (const float*)d_in[14]; const float* pb1 = (const float*)d_in[15];
    const float* pw2 = (const float*)d_in[16]; const float* pb2 = (const float*)d_in[17];
    const float* cw1 = (const float*)d_in[18]; const float* cb1 = (const float*)d_in[19];
    const float* cw2 = (const float*)d_in[20]; const float* cb2 = (const float*)d_in[21];
    float* out = (float*)d_out;

    int nthr = (NB_SCAN * 256 > N_GRAPHS * HID) ? NB_SCAN * 256 : N_GRAPHS * HID;

    // prep + CSR build
    k_prep<<<1, 384>>>(bn_gamma, bn_beta, bn_mean, bn_var,
                       pocket, pw1, pb1, pw2, pb2);
    k_prepW<<<(HID * HID + 255) / 256, 256>>>(W1, W2);
    k_zero_misc<<<(nthr + 255) / 256, 256>>>();
    k_count<<<(N_EDGES + 255) / 256, 256>>>(dst);
    k_scan1<<<NB_SCAN, 256>>>();
    k_scan2<<<1, 512>>>();
    k_scan3<<<NB_SCAN, 256>>>();
    k_fill<<<(N_EDGES + 255) / 256, 256>>>(src, dst);

    int tc_grid = (N_NODES + 127) / 128;          // 782 full tiles (padded bufs)
    int node_warp_grid = (N_NODES + 7) / 8;

    // layer 0
    k_gemm0<<<node_warp_grid, 256>>>(x, W0);
    k_gather<<<node_warp_grid, 256>>>(b0, 0, 1);  // BN0+ReLU+tf32 round
    // layer 1
    k_gemm128_tc<<<tc_grid, 256>>>(0);
    k_gather<<<node_warp_grid, 256>>>(b1, 1, 1);  // BN1+ReLU+tf32 round
    // layer 2
    k_gemm128_tc<<<tc_grid, 256>>>(1);
    k_gather<<<node_warp_grid, 256>>>(b2, 2, 0);  // BN2+ReLU, full fp32

    // pooling + head
    k_pool<<<node_warp_grid, 256>>>(batch);
    k_head<<<N_GRAPHS, 96>>>(cw1, cb1, cw2, cb2, out);
}